// round 12
// baseline (speedup 1.0000x reference)
#include <cuda_runtime.h>
#include <cuda_fp16.h>
#include <cstdint>
#include <math.h>

#define BB 4
#define SQ 2048
#define HH 1024
#define DD 64
#define MT (BB*SQ)   // 8192

// ---------------- scratch ----------------
__device__ __align__(16) __half g_qh[MT*DD];
__device__ __align__(16) __half g_kh[MT*DD];
__device__ __align__(16) __half g_vh[MT*DD];
__device__ __align__(16) __half g_hh[MT*DD], g_hl[MT*DD];         // head hi/lo
__device__ __align__(16) __half g_WTh[3*DD*HH], g_WTl[3*DD*HH];   // [sel][n=64][k=1024]
__device__ __align__(16) __half g_WeffTh[HH*DD], g_WeffTl[HH*DD]; // [j=1024][d=64]
__device__ float g_Gpart[BB*16*DD*DD];
__device__ float g_Kspart[BB*16*DD];
__device__ float g_G[BB*DD*DD];
__device__ float g_Ksum[BB*DD];
__device__ float g_c0[MT], g_c1[MT];

// ---------------- helpers ----------------
__device__ __forceinline__ uint32_t su32(const void* p){
    uint32_t a;
    asm("{ .reg .u64 t; cvta.to.shared.u64 t, %1; cvt.u32.u64 %0, t; }" : "=r"(a) : "l"(p));
    return a;
}
__device__ __forceinline__ void ldsm4(uint32_t& r0,uint32_t& r1,uint32_t& r2,uint32_t& r3,uint32_t a){
    asm volatile("ldmatrix.sync.aligned.m8n8.x4.shared.b16 {%0,%1,%2,%3}, [%4];"
                 : "=r"(r0),"=r"(r1),"=r"(r2),"=r"(r3) : "r"(a));
}
__device__ __forceinline__ void ldsm2(uint32_t& r0,uint32_t& r1,uint32_t a){
    asm volatile("ldmatrix.sync.aligned.m8n8.x2.shared.b16 {%0,%1}, [%2];"
                 : "=r"(r0),"=r"(r1) : "r"(a));
}
__device__ __forceinline__ void ldsm2t(uint32_t& r0,uint32_t& r1,uint32_t a){
    asm volatile("ldmatrix.sync.aligned.m8n8.x2.trans.shared.b16 {%0,%1}, [%2];"
                 : "=r"(r0),"=r"(r1) : "r"(a));
}
__device__ __forceinline__ void mma16816(float* c, const uint32_t* a, uint32_t b0, uint32_t b1){
    asm volatile("mma.sync.aligned.m16n8k16.row.col.f32.f16.f16.f32 "
                 "{%0,%1,%2,%3}, {%4,%5,%6,%7}, {%8,%9}, {%0,%1,%2,%3};"
                 : "+f"(c[0]),"+f"(c[1]),"+f"(c[2]),"+f"(c[3])
                 : "r"(a[0]),"r"(a[1]),"r"(a[2]),"r"(a[3]), "r"(b0),"r"(b1));
}
#define CPA(dst,src) asm volatile("cp.async.cg.shared.global [%0], [%1], 16;" :: "r"(dst),"l"(src))
#define CPC() asm volatile("cp.async.commit_group;" ::: "memory")
#define CPW(n) asm volatile("cp.async.wait_group %0;" :: "n"(n) : "memory")

__device__ __forceinline__ uint32_t cvt2h(float x, float y){
    __half2 h = __floats2half2_rn(x,y);
    return *(uint32_t*)&h;
}
__device__ __forceinline__ void split_pair(float x, float y, uint32_t& hi, uint32_t& lo){
    __half2 h = __floats2half2_rn(x,y);
    float2 f = __half22float2(h);
    __half2 l = __floats2half2_rn(x - f.x, y - f.y);
    hi = *(uint32_t*)&h; lo = *(uint32_t*)&l;
}

// ---------------- prep: hi/lo W^T + folded Weff^T ----------------
__global__ void k_prep(const float* __restrict__ Wq, const float* __restrict__ Wk,
                       const float* __restrict__ Wv, const float* __restrict__ Wout){
    int idx = blockIdx.x*256 + threadIdx.x;   // 262144
    if (idx < 3*65536) {
        int w = idx >> 16, r = idx & 65535, n = r >> 10, k = r & 1023;
        const float* W = w==0 ? Wq : (w==1 ? Wk : Wv);
        float x = W[k*DD + n];
        __half h = __float2half(x);
        g_WTh[idx] = h;
        g_WTl[idx] = __float2half(x - __half2float(h));
    } else {
        int r = idx - 3*65536, j = r >> 6, d = r & 63;
        float s = 0.f;
#pragma unroll
        for (int h = 0; h < 16; ++h) s += Wout[(h*DD + d)*HH + j];
        __half hh = __float2half(s);
        g_WeffTh[j*DD + d] = hh;
        g_WeffTl[j*DD + d] = __float2half(s - __half2float(hh));
    }
}

// ---------------- projection via mma + fused Gram (sel==1) ----------------
#define PP 40
__global__ __launch_bounds__(256) void k_proj_mma(
    const float* __restrict__ Xq, const float* __restrict__ Xk, const float* __restrict__ Xv,
    const float* __restrict__ bq, const float* __restrict__ bk, const float* __restrict__ bv)
{
    __shared__ __align__(16) char pbuf[33536];
    __half* Xh = (__half*)pbuf;
    __half* Wh = (__half*)(pbuf + 10240);
    __half* Wl = (__half*)(pbuf + 15360);
    float*  Ks2 = (float*)pbuf;

    const int t = threadIdx.x, w = t>>5, lane = t&31;
    const int sel = blockIdx.y, m0 = blockIdx.x*128;
    const int wm = w&3, wn = w>>2;
    const float* X    = sel==0?Xq:(sel==1?Xk:Xv);
    const float* bias = sel==0?bq:(sel==1?bk:bv);
    const __half* WTh = g_WTh + sel*65536;
    const __half* WTl = g_WTl + sel*65536;

    const int i8 = lane&7, q4 = lane>>3;
    const int mrow = i8 + ((q4&1)<<3), kcol = (q4>>1)<<3;
    const int s2 = (lane>>3)&1;
    const uint32_t xh_b = su32(Xh), wh_b = su32(Wh), wl_b = su32(Wl);

    float acc[2][4][4];
#pragma unroll
    for (int a=0;a<2;++a)
#pragma unroll
        for (int bq_=0;bq_<4;++bq_)
#pragma unroll
            for (int cq=0;cq<4;++cq) acc[a][bq_][cq]=0.f;

    float4 xr[4]; uint4 whr, wlr;
    auto LD = [&](int c){
        int k0 = c*32;
#pragma unroll
        for (int i=0;i<4;++i){ int id=t+i*256, row=id>>3, c4=id&7;
            xr[i] = *(const float4*)&X[(size_t)(m0+row)*HH + k0 + c4*4]; }
        { int row = t>>2, cc = t&3;
          whr = *(const uint4*)(WTh + (size_t)row*HH + k0 + cc*8);
          wlr = *(const uint4*)(WTl + (size_t)row*HH + k0 + cc*8); }
    };
    auto ST = [&](){
#pragma unroll
        for (int i=0;i<4;++i){ int id=t+i*256, row=id>>3, c4=id&7;
            *(uint2*)&Xh[row*PP + c4*4] =
                make_uint2(cvt2h(xr[i].x, xr[i].y), cvt2h(xr[i].z, xr[i].w)); }
        { int row = t>>2, cc = t&3;
          *(uint4*)&Wh[row*PP + cc*8] = whr;
          *(uint4*)&Wl[row*PP + cc*8] = wlr; }
    };

    LD(0); ST(); __syncthreads();
    for (int c=0;c<32;++c){
        if (c<31) LD(c+1);
#pragma unroll
        for (int ks=0;ks<2;++ks){
            uint32_t ah[2][4];
#pragma unroll
            for (int mt=0;mt<2;++mt){
                uint32_t ra = (uint32_t)(((wm*32+mt*16+mrow)*PP + ks*16 + kcol)*2);
                ldsm4(ah[mt][0],ah[mt][1],ah[mt][2],ah[mt][3], xh_b + ra);
            }
#pragma unroll
            for (int nt=0;nt<4;++nt){
                uint32_t rb = (uint32_t)(((wn*32+nt*8+i8)*PP + ks*16 + s2*8)*2);
                uint32_t bh0,bh1,bl0,bl1;
                ldsm2(bh0,bh1, wh_b + rb);
                ldsm2(bl0,bl1, wl_b + rb);
#pragma unroll
                for (int mt=0;mt<2;++mt){
                    mma16816(acc[mt][nt], ah[mt], bh0, bh1);
                    mma16816(acc[mt][nt], ah[mt], bl0, bl1);
                }
            }
        }
        __syncthreads();
        if (c<31){ ST(); __syncthreads(); }
    }

    const int g4 = lane>>2, tq = lane&3;
#pragma unroll
    for (int mt=0;mt<2;++mt)
#pragma unroll
    for (int nt=0;nt<4;++nt){
        int n = wn*32 + nt*8 + tq*2;
        float2 bb = __ldg((const float2*)&bias[n]);
#pragma unroll
        for (int hf=0;hf<2;++hf){
            int rowl = wm*32 + mt*16 + g4 + hf*8;
            float v0 = acc[mt][nt][hf*2+0] + bb.x;
            float v1 = acc[mt][nt][hf*2+1] + bb.y;
            size_t o = (size_t)(m0 + rowl)*DD + n;
            if (sel == 0){
                *(uint32_t*)(g_qh + o) = cvt2h(v0, v1);
            } else if (sel == 1){
                *(uint32_t*)(g_kh + o) = cvt2h(v0, v1);
                Ks2[rowl*65 + n]   = v0;
                Ks2[rowl*65 + n+1] = v1;
            } else {
                *(uint32_t*)(g_vh + o) = cvt2h(v0, v1);
            }
        }
    }

    if (sel == 1){
        __syncthreads();
        int a = t >> 2, b0 = (t & 3) * 16;
        float gacc[16];
#pragma unroll
        for (int i = 0; i < 16; ++i) gacc[i] = 0.f;
        for (int j = 0; j < 128; ++j) {
            float ka = Ks2[j*65 + a];
#pragma unroll
            for (int bb = 0; bb < 16; ++bb) gacc[bb] += ka * Ks2[j*65 + b0 + bb];
        }
        int bB = m0 >> 11, cb = (m0 >> 7) & 15;
        float* gp = g_Gpart + (size_t)(bB*16 + cb)*4096;
#pragma unroll
        for (int bb = 0; bb < 16; ++bb) gp[a*64 + b0 + bb] = gacc[bb];
        if (t < 64) {
            float s = 0.f;
            for (int j = 0; j < 128; ++j) s += Ks2[j*65 + t];
            g_Kspart[(bB*16 + cb)*64 + t] = s;
        }
    }
}

// ---------------- Gram reduce ----------------
__global__ void k_gramred() {
    int idx = blockIdx.x * 256 + threadIdx.x;
    if (idx < BB*4096) {
        int b = idx >> 12, e = idx & 4095;
        float s = 0.f;
#pragma unroll
        for (int c = 0; c < 16; ++c) s += g_Gpart[(size_t)(b*16+c)*4096 + e];
        g_G[idx] = s;
    } else if (idx < BB*4096 + BB*64) {
        int r = idx - BB*4096, b = r >> 6, e = r & 63;
        float s = 0.f;
#pragma unroll
        for (int c = 0; c < 16; ++c) s += g_Kspart[(b*16+c)*64 + e];
        g_Ksum[r] = s;
    }
}

// ---------------- per-query layernorm constants ----------------
#define STATS_SMEM ((4096 + 64 + 256*65)*4)
__global__ __launch_bounds__(256) void k_stats() {
    extern __shared__ float ss[];
    float* Gs = ss; float* Ks = Gs + 4096; float* qs = Ks + 64;
    const int t = threadIdx.x, b = blockIdx.y, q0 = blockIdx.x*256;
    for (int id = t; id < 4096; id += 256) Gs[id] = g_G[b*4096 + id];
    if (t < 64) Ks[t] = g_Ksum[b*64 + t];
    const __half* qp = g_qh + (size_t)(b*SQ + q0)*DD;
    for (int id = t; id < 2048; id += 256) {
        int row = id >> 3, c = (id & 7) * 8;
        uint4 v = *(const uint4*)(qp + (size_t)row*DD + c);
        const __half2* h2 = (const __half2*)&v;
#pragma unroll
        for (int j = 0; j < 4; ++j){
            float2 f = __half22float2(h2[j]);
            qs[row*65 + c + 2*j]   = f.x;
            qs[row*65 + c + 2*j+1] = f.y;
        }
    }
    __syncthreads();
    float su = 0.f, sq = 0.f;
    for (int a = 0; a < 64; ++a) {
        float qa = qs[t*65 + a];
        su += qa * Ks[a];
        float ta = 0.f;
#pragma unroll 16
        for (int bb = 0; bb < 64; ++bb) ta += Gs[a*64 + bb] * qs[t*65 + bb];
        sq += qa * ta;
    }
    float mu  = su * (1.f/(32.f*(float)SQ));
    float var = (sq*(1.f/1024.f) - (float)SQ*mu*mu) * (1.f/((float)SQ - 1.f));
    float rinv = 1.f / (sqrtf(var) + 1e-8f);
    g_c1[b*SQ + q0 + t] = rinv * (1.f/32.f);
    g_c0[b*SQ + q0 + t] = -mu * rinv;
}

// ---------------- flash attention -> head (hi/lo f16) ----------------
// 512 threads, 16 warps: wm=w&1 (32-row half), wn=w>>1 (16-key slice)
#define OQH 0u
#define OC0a 9216u
#define ORED 9472u          // 8*64 floats
#define OKV 11520u
#define KVB 36864u          // Kh +0, Vh +18432
#define ATTN_SMEM (OKV + 2*KVB)   // 85248
#define AP 72

__global__ __launch_bounds__(512) void k_attn_mma()
{
    extern __shared__ __align__(16) char smc[];
    const uint32_t sb = su32(smc);
    const int t = threadIdx.x, w = t>>5, lane = t&31;
    const int b = blockIdx.y, qbase = blockIdx.x*64;
    const int wm = w&1, wn = w>>1;
    const int i8 = lane&7, q4 = lane>>3;
    const int mrow = i8 + ((q4&1)<<3), kcol = (q4>>1)<<3;
    const int s2 = (lane>>3)&1;
    const int g4 = lane>>2, tq = lane&3;

    auto issue = [&](int kc, int bf){
        uint32_t dbase = sb + OKV + (uint32_t)bf*KVB;
        size_t g0 = ((size_t)b*SQ + (size_t)kc*128)*DD;
#pragma unroll
        for (int i=0;i<2;++i){
            int id = t + i*512, row = id>>3, c = id&7;
            uint32_t doff = (uint32_t)(row*144 + c*16);
            size_t so = g0 + (size_t)row*DD + c*8;
            CPA(dbase + doff,          g_kh + so);
            CPA(dbase + 18432u + doff, g_vh + so);
        }
        CPC();
    };
    issue(0, 0);

    // Q tile (f16, 64 rows)
    {
        int row = t>>3, c = t&7;
        size_t so = ((size_t)(b*SQ + qbase) + row)*DD + c*8;
        *(uint4*)(smc + OQH + row*144 + c*16) = *(const uint4*)(g_qh + so);
    }
    float c0v[2][2], c1v[2][2];
#pragma unroll
    for (int mt=0;mt<2;++mt)
#pragma unroll
        for (int hf=0;hf<2;++hf){
            int row = wm*32 + mt*16 + g4 + hf*8;
            c0v[mt][hf] = __ldg(&g_c0[b*SQ + qbase + row]);
            c1v[mt][hf] = __ldg(&g_c1[b*SQ + qbase + row]);
        }
    __syncthreads();

    float oc[2][8][4];
#pragma unroll
    for (int a=0;a<2;++a)
#pragma unroll
        for (int n=0;n<8;++n)
#pragma unroll
            for (int c=0;c<4;++c) oc[a][n][c]=0.f;
    float lacc[4] = {0.f,0.f,0.f,0.f};

    for (int kc=0;kc<16;++kc){
        if (kc<15){ issue(kc+1, (kc+1)&1); CPW(1); } else { CPW(0); }
        __syncthreads();
        const uint32_t kb = sb + OKV + (uint32_t)((kc&1)*KVB);

        float sa[2][2][4];
#pragma unroll
        for (int a=0;a<2;++a)
#pragma unroll
            for (int n=0;n<2;++n)
#pragma unroll
                for (int c=0;c<4;++c) sa[a][n][c]=0.f;
#pragma unroll
        for (int ks=0;ks<4;++ks){
            uint32_t ah[2][4];
#pragma unroll
            for (int mt=0;mt<2;++mt){
                uint32_t ra = (uint32_t)(((wm*32+mt*16+mrow)*AP + ks*16 + kcol)*2);
                ldsm4(ah[mt][0],ah[mt][1],ah[mt][2],ah[mt][3], sb + OQH + ra);
            }
#pragma unroll
            for (int nt=0;nt<2;++nt){
                uint32_t rb = kb + (uint32_t)(((wn*16+nt*8+i8)*AP + ks*16 + s2*8)*2);
                uint32_t bh0,bh1;
                ldsm2(bh0,bh1, rb);
#pragma unroll
                for (int mt=0;mt<2;++mt)
                    mma16816(sa[mt][nt], ah[mt], bh0, bh1);
            }
        }
#pragma unroll
        for (int mt=0;mt<2;++mt)
#pragma unroll
        for (int nt=0;nt<2;++nt){
            float* s4 = sa[mt][nt];
            s4[0] = __expf(fmaf(s4[0], c1v[mt][0], c0v[mt][0]));
            s4[1] = __expf(fmaf(s4[1], c1v[mt][0], c0v[mt][0]));
            s4[2] = __expf(fmaf(s4[2], c1v[mt][1], c0v[mt][1]));
            s4[3] = __expf(fmaf(s4[3], c1v[mt][1], c0v[mt][1]));
            lacc[mt*2+0] += s4[0]+s4[1];
            lacc[mt*2+1] += s4[2]+s4[3];
        }
        {
            uint32_t pah[2][4];
#pragma unroll
            for (int mt=0;mt<2;++mt){
                pah[mt][0] = cvt2h(sa[mt][0][0], sa[mt][0][1]);
                pah[mt][1] = cvt2h(sa[mt][0][2], sa[mt][0][3]);
                pah[mt][2] = cvt2h(sa[mt][1][0], sa[mt][1][1]);
                pah[mt][3] = cvt2h(sa[mt][1][2], sa[mt][1][3]);
            }
#pragma unroll
            for (int nt=0;nt<8;++nt){
                uint32_t va = kb + 18432u +
                    (uint32_t)(((wn*16 + i8 + s2*8)*AP + nt*8)*2);
                uint32_t bh0,bh1;
                ldsm2t(bh0,bh1, va);
#pragma unroll
                for (int mt=0;mt<2;++mt)
                    mma16816(oc[mt][nt], pah[mt], bh0, bh1);
            }
        }
        __syncthreads();
    }

    // rowsum reduce
#pragma unroll
    for (int i=0;i<4;++i){
        lacc[i] += __shfl_xor_sync(0xffffffffu, lacc[i], 1);
        lacc[i] += __shfl_xor_sync(0xffffffffu, lacc[i], 2);
    }
    if (tq == 0){
#pragma unroll
        for (int mt=0;mt<2;++mt)
#pragma unroll
            for (int hf=0;hf<2;++hf)
                ((float*)(smc+ORED))[wn*64 + wm*32 + mt*16 + g4 + hf*8] = lacc[mt*2+hf];
    }
    // partial O -> smem (8 wn groups into 4 buffers, two passes)
    {
        float* ob = (float*)(smc + OKV + (size_t)(wn&3)*17408);
        if (wn < 4){
#pragma unroll
            for (int mt=0;mt<2;++mt)
#pragma unroll
            for (int nt=0;nt<8;++nt){
                int r0 = wm*32 + mt*16 + g4, cc = nt*8 + tq*2;
                *(float2*)&ob[r0*68 + cc]     = make_float2(oc[mt][nt][0], oc[mt][nt][1]);
                *(float2*)&ob[(r0+8)*68 + cc] = make_float2(oc[mt][nt][2], oc[mt][nt][3]);
            }
        }
        __syncthreads();
        if (wn >= 4){
#pragma unroll
            for (int mt=0;mt<2;++mt)
#pragma unroll
            for (int nt=0;nt<8;++nt){
                int r0 = wm*32 + mt*16 + g4, cc = nt*8 + tq*2;
                float2 a0 = *(float2*)&ob[r0*68 + cc];
                float2 a1 = *(float2*)&ob[(r0+8)*68 + cc];
                *(float2*)&ob[r0*68 + cc]     = make_float2(a0.x + oc[mt][nt][0], a0.y + oc[mt][nt][1]);
                *(float2*)&ob[(r0+8)*68 + cc] = make_float2(a1.x + oc[mt][nt][2], a1.y + oc[mt][nt][3]);
            }
        }
    }
    __syncthreads();
    if (t < 64){
        float s = 0.f;
#pragma unroll
        for (int wq=0;wq<8;++wq) s += ((float*)(smc+ORED))[wq*64 + t];
        ((float*)(smc+OC0a))[t] = 1.f / s;
    }
    __syncthreads();
    // head = (sum of 4 ob) * linv -> f16 hi/lo to GLOBAL
    for (int id = t; id < 2048; id += 512){
        int row = id >> 5, d2 = (id & 31) * 2;
        float o0 = 0.f, o1 = 0.f;
#pragma unroll
        for (int wq=0;wq<4;++wq){
            const float* ob = (const float*)(smc + OKV + (size_t)wq*17408);
            o0 += ob[row*68 + d2];
            o1 += ob[row*68 + d2 + 1];
        }
        float li = ((float*)(smc+OC0a))[row];
        uint32_t hi, lo;
        split_pair(o0*li, o1*li, hi, lo);
        size_t go = ((size_t)(b*SQ + qbase) + row)*DD + d2;
        *(uint32_t*)(g_hh + go) = hi;
        *(uint32_t*)(g_hl + go) = lo;
    }
}

// ---------------- output GEMM: out = head @ Weff + bout ----------------
// grid (8, 64): jt = 128-col tile, m-tile = 128 rows. 256 threads.
#define GHH 0u
#define GHL 18432u
#define GWH 36864u
#define GWL 55296u
#define OUT_SMEM 73728
__global__ __launch_bounds__(256) void k_out(const float* __restrict__ bout,
                                             float* __restrict__ out)
{
    extern __shared__ __align__(16) char smo[];
    const uint32_t sb = su32(smo);
    const int t = threadIdx.x, w = t>>5, lane = t&31;
    const int jt = blockIdx.x, m0 = blockIdx.y*128;
    const int wm = w&3, wn = w>>2;
    const int i8 = lane&7, q4 = lane>>3;
    const int mrow = i8 + ((q4&1)<<3), kcol = (q4>>1)<<3;
    const int s2 = (lane>>3)&1;
    const int g4 = lane>>2, tq = lane&3;

    // load head tile (hi/lo) + Weff tile (hi/lo)
#pragma unroll
    for (int i=0;i<4;++i){
        int id = t + i*256, row = id>>3, c = id&7;
        uint32_t doff = (uint32_t)(row*144 + c*16);
        size_t ho = ((size_t)(m0 + row))*DD + c*8;
        size_t wo = ((size_t)(jt*128 + row))*DD + c*8;
        *(uint4*)(smo + GHH + doff) = *(const uint4*)(g_hh + ho);
        *(uint4*)(smo + GHL + doff) = *(const uint4*)(g_hl + ho);
        *(uint4*)(smo + GWH + doff) = *(const uint4*)(g_WeffTh + wo);
        *(uint4*)(smo + GWL + doff) = *(const uint4*)(g_WeffTl + wo);
    }
    __syncthreads();

    float acc[2][8][4];
#pragma unroll
    for (int a=0;a<2;++a)
#pragma unroll
        for (int n=0;n<8;++n)
#pragma unroll
            for (int c=0;c<4;++c) acc[a][n][c]=0.f;
#pragma unroll
    for (int ks=0;ks<4;++ks){
        uint32_t ah[2][4], al[2][4];
#pragma unroll
        for (int mt=0;mt<2;++mt){
            uint32_t ra = (uint32_t)(((wm*32+mt*16+mrow)*AP + ks*16 + kcol)*2);
            ldsm4(ah[mt][0],ah[mt][1],ah[mt][2],ah[mt][3], sb + GHH + ra);
            ldsm4(al[mt][0],al[mt][1],al[mt][2],al[mt][3], sb + GHL + ra);
        }
#pragma unroll
        for (int nt=0;nt<8;++nt){
            uint32_t rb = (uint32_t)(((wn*64+nt*8+i8)*AP + ks*16 + s2*8)*2);
            uint32_t bh0,bh1,bl0,bl1;
            ldsm2(bh0,bh1, sb + GWH + rb);
            ldsm2(bl0,bl1, sb + GWL + rb);
#pragma unroll
            for (int mt=0;mt<2;++mt){
                mma16816(acc[mt][nt], ah[mt], bh0, bh1);
                mma16816(acc[mt][nt], ah[mt], bl0, bl1);
                mma16816(acc[mt][nt], al[mt], bh0, bh1);
            }
        }
    }
    __syncthreads();
    // stage 128x128 with bias (pitch 132), then coalesced write
    float* stage = (float*)smo;
#pragma unroll
    for (int mt=0;mt<2;++mt)
#pragma unroll
    for (int nt=0;nt<8;++nt){
        int colL = wn*64 + nt*8 + tq*2;
        float2 bb = __ldg((const float2*)&bout[jt*128 + colL]);
#pragma unroll
        for (int hf=0;hf<2;++hf){
            int row = wm*32 + mt*16 + g4 + hf*8;
            *(float2*)&stage[row*132 + colL] =
                make_float2(acc[mt][nt][hf*2+0] + bb.x, acc[mt][nt][hf*2+1] + bb.y);
        }
    }
    __syncthreads();
    float* orow = out + (size_t)m0*HH + jt*128;
#pragma unroll
    for (int i=0;i<16;++i){
        int id = t + i*256, row = id>>5, c4 = (id&31)*4;
        *(float4*)&orow[(size_t)row*HH + c4] = *(float4*)&stage[row*132 + c4];
    }
}

// ---------------------------------------------------------------------------
extern "C" void kernel_launch(void* const* d_in, const int* in_sizes, int n_in,
                              void* d_out, int out_size)
{
    (void)in_sizes; (void)n_in; (void)out_size;
    const float* query = (const float*)d_in[0];
    const float* key   = (const float*)d_in[1];
    const float* value = (const float*)d_in[2];
    const float* Wq   = (const float*)d_in[4];
    const float* bq   = (const float*)d_in[5];
    const float* Wk   = (const float*)d_in[6];
    const float* bk   = (const float*)d_in[7];
    const float* Wv   = (const float*)d_in[8];
    const float* bv   = (const float*)d_in[9];
    const float* Wout = (const float*)d_in[10];
    const float* bo   = (const float*)d_in[11];
    float* out = (float*)d_out;

    cudaFuncSetAttribute(k_stats,    cudaFuncAttributeMaxDynamicSharedMemorySize, STATS_SMEM);
    cudaFuncSetAttribute(k_attn_mma, cudaFuncAttributeMaxDynamicSharedMemorySize, ATTN_SMEM);
    cudaFuncSetAttribute(k_out,      cudaFuncAttributeMaxDynamicSharedMemorySize, OUT_SMEM);

    k_prep<<<1024, 256>>>(Wq, Wk, Wv, Wout);
    k_proj_mma<<<dim3(64,3), 256>>>(query, key, value, bq, bk, bv);
    k_gramred<<<66, 256>>>();
    k_stats<<<dim3(8,BB), 256, STATS_SMEM>>>();
    k_attn_mma<<<dim3(32,BB), 512, ATTN_SMEM>>>();
    k_out<<<dim3(8,64), 256, OUT_SMEM>>>(bo, out);
}